// round 1
// baseline (speedup 1.0000x reference)
#include <cuda_runtime.h>
#include <math.h>

#define Bn 8
#define Hn 256
#define Wn 256
#define ROWS (Bn*Hn)          // 2048
#define NPIX (Bn*Hn*Wn)       // 524288
#define INF_F 1e10f

// Scratch: squared row-pass EDT results
__device__ float g_out_buf[NPIX];   // sq dist (along W) to nearest t==1  -> EDT(1-t)
__device__ float g_in_buf[NPIX];    // sq dist (along W) to nearest t==0  -> EDT(t)

// Accumulators
__device__ double acc_spt[Bn];   // sum p*t per batch
__device__ double acc_sp2[Bn];   // sum p^2 per batch
__device__ double acc_st[Bn];    // sum t   per batch (t^2 == t)
__device__ double acc_bsum;      // sum p * dist over all pixels

__global__ void init_acc_kernel() {
    int i = threadIdx.x;
    if (i < Bn) { acc_spt[i] = 0.0; acc_sp2[i] = 0.0; acc_st[i] = 0.0; }
    if (i == Bn) acc_bsum = 0.0;
}

__device__ __forceinline__ float sigmoidf_(float x) {
    return 1.0f / (1.0f + expf(-x));
}

// One block per (b,h) row. Computes row-pass EDT (O(n) scans) and dice partial sums.
__global__ void row_edt_kernel(const float* __restrict__ pred,
                               const float* __restrict__ target,
                               const int* __restrict__ flg) {
    __shared__ float tsh[Wn];
    __shared__ int n1[Wn];   // nearest-one distance
    __shared__ int n0[Wn];   // nearest-zero distance
    __shared__ float rs[3][8];

    int row = blockIdx.x;            // 0..2047
    int b   = row >> 8;
    int tid = threadIdx.x;

    const float* trow = target + (size_t)row * Wn;
    const float* prow = pred   + (size_t)row * Wn;

    float t = trow[tid];
    tsh[tid] = t;

    // dice partials (sigmoid applied per from_logits flag)
    float p = prow[tid];
    if (flg[0]) p = sigmoidf_(p);
    float spt = p * t;
    float sp2 = p * p;
    float st  = t;

    // warp reduce
    unsigned lane = tid & 31u, wid = tid >> 5;
    #pragma unroll
    for (int o = 16; o; o >>= 1) {
        spt += __shfl_down_sync(0xffffffffu, spt, o);
        sp2 += __shfl_down_sync(0xffffffffu, sp2, o);
        st  += __shfl_down_sync(0xffffffffu, st,  o);
    }
    if (lane == 0) { rs[0][wid] = spt; rs[1][wid] = sp2; rs[2][wid] = st; }

    __syncthreads();

    if (tid == 0) {
        // block-level dice sums
        float A = 0.f, Bv = 0.f, C = 0.f;
        #pragma unroll
        for (int w = 0; w < 8; w++) { A += rs[0][w]; Bv += rs[1][w]; C += rs[2][w]; }
        atomicAdd(&acc_spt[b], (double)A);
        atomicAdd(&acc_sp2[b], (double)Bv);
        atomicAdd(&acc_st[b],  (double)C);

        // sequential two-sweep nearest distance (exact)
        int d1 = 1 << 20, d0 = 1 << 20;
        for (int j = 0; j < Wn; j++) {
            bool one = tsh[j] > 0.5f;
            d1 = one ? 0 : d1 + 1;
            d0 = one ? d0 + 1 : 0;
            n1[j] = d1; n0[j] = d0;
        }
        d1 = 1 << 20; d0 = 1 << 20;
        for (int j = Wn - 1; j >= 0; j--) {
            bool one = tsh[j] > 0.5f;
            d1 = one ? 0 : d1 + 1;
            d0 = one ? d0 + 1 : 0;
            n1[j] = min(n1[j], d1);
            n0[j] = min(n0[j], d0);
        }
    }
    __syncthreads();

    {
        int a1 = n1[tid];
        int a0 = n0[tid];
        size_t o = (size_t)row * Wn + tid;
        g_out_buf[o] = (a1 <= Wn - 1) ? (float)(a1 * a1) : INF_F;
        g_in_buf[o]  = (a0 <= Wn - 1) ? (float)(a0 * a0) : INF_F;
    }
}

// Column pass: brute-force min-plus along H on g_out/g_in, then boundary sum.
// Block handles (b, 8 columns). 256 threads: wl = tid%8 column, ig = tid/8,
// each thread computes outputs i = ig + 32k, k=0..7.
#define WT 8
__global__ void col_edt_kernel(const float* __restrict__ pred,
                               const int* __restrict__ flg) {
    __shared__ float csh[Hn * WT];          // c[j][w'] = g[b][j][w0+w'] + j^2
    __shared__ double red[8];

    int tid = threadIdx.x;
    int b   = blockIdx.x >> 5;              // 8 batches
    int w0  = (blockIdx.x & 31) * WT;       // 32 column-tiles
    int wl  = tid & (WT - 1);
    int ig  = tid >> 3;                     // 0..31

    float s[8];                             // accumulated distances per output i

    #pragma unroll
    for (int pass = 0; pass < 2; pass++) {
        const float* gb = (pass == 0) ? g_out_buf : g_in_buf;
        __syncthreads();
        // cooperative tile load, fold j^2
        #pragma unroll
        for (int r = 0; r < 8; r++) {
            int idx = tid + 256 * r;
            int j = idx >> 3;
            int wq = idx & (WT - 1);
            float v = gb[((size_t)(b * Hn + j)) * Wn + w0 + wq];
            float jf = (float)j;
            csh[idx] = fmaf(jf, jf, v);
        }
        __syncthreads();

        float m[8], a[8];
        #pragma unroll
        for (int k = 0; k < 8; k++) {
            m[k] = 3.0e38f;
            a[k] = -2.0f * (float)(ig + 32 * k);
        }
        float jf = 0.0f;
        for (int j = 0; j < Hn; j++) {
            float c = csh[j * WT + wl];
            #pragma unroll
            for (int k = 0; k < 8; k++)
                m[k] = fminf(m[k], fmaf(a[k], jf, c));
            jf += 1.0f;
        }
        #pragma unroll
        for (int k = 0; k < 8; k++) {
            float fi = (float)(ig + 32 * k);
            float h = fmaf(fi, fi, m[k]);   // exact for finite case
            float d = sqrtf(h);
            if (pass == 0) s[k] = d; else s[k] += d;
        }
    }

    // boundary loss partial: sum sigmoid(pred) * dist
    int fl = flg[0];
    double lsum = 0.0;
    #pragma unroll
    for (int k = 0; k < 8; k++) {
        int i = ig + 32 * k;
        float pv = pred[((size_t)(b * Hn + i)) * Wn + w0 + wl];
        if (fl) pv = sigmoidf_(pv);
        lsum += (double)(pv * s[k]);
    }
    // block reduce (double)
    unsigned lane = tid & 31u, wid = tid >> 5;
    #pragma unroll
    for (int o = 16; o; o >>= 1)
        lsum += __shfl_down_sync(0xffffffffu, lsum, o);
    if (lane == 0) red[wid] = lsum;
    __syncthreads();
    if (tid == 0) {
        double tot = 0.0;
        #pragma unroll
        for (int w = 0; w < 8; w++) tot += red[w];
        atomicAdd(&acc_bsum, tot);
    }
}

__global__ void finalize_kernel(float* __restrict__ out) {
    double d = 0.0;
    #pragma unroll
    for (int b = 0; b < Bn; b++) {
        double inter = 2.0 * acc_spt[b];
        double uni   = acc_sp2[b] + acc_st[b];
        d += 1.0 - (inter + 1e-6) / (uni + 1e-6);
    }
    d *= (1.0 / (double)Bn);
    double bl = acc_bsum * (1.0 / (double)NPIX);
    out[0] = (float)(d + bl);
}

extern "C" void kernel_launch(void* const* d_in, const int* in_sizes, int n_in,
                              void* d_out, int out_size) {
    const float* pred   = (const float*)d_in[0];
    const float* target = (const float*)d_in[1];
    const int*   flg    = (const int*)d_in[2];
    float* out = (float*)d_out;

    init_acc_kernel<<<1, 32>>>();
    row_edt_kernel<<<ROWS, Wn>>>(pred, target, flg);
    col_edt_kernel<<<Bn * (Wn / WT), 256>>>(pred, flg);
    finalize_kernel<<<1, 1>>>(out);
}

// round 2
// speedup vs baseline: 1.0067x; 1.0067x over previous
#include <cuda_runtime.h>
#include <math.h>

#define Bn 8
#define Hn 256
#define Wn 256
#define ROWS (Bn*Hn)          // 2048
#define NPIX (Bn*Hn*Wn)       // 524288
#define INF_F 1e10f

// Scratch: squared row-pass EDT results
__device__ float g_out_buf[NPIX];   // sq dist (along W) to nearest t==1  -> EDT(1-t)
__device__ float g_in_buf[NPIX];    // sq dist (along W) to nearest t==0  -> EDT(t)

// Accumulators
__device__ double acc_spt[Bn];   // sum p*t per batch
__device__ double acc_sp2[Bn];   // sum p^2 per batch
__device__ double acc_st[Bn];    // sum t   per batch (t^2 == t)
__device__ double acc_bsum;      // sum p * dist over all pixels

__global__ void init_acc_kernel() {
    int i = threadIdx.x;
    if (i < Bn) { acc_spt[i] = 0.0; acc_sp2[i] = 0.0; acc_st[i] = 0.0; }
    if (i == Bn) acc_bsum = 0.0;
}

__device__ __forceinline__ float sigmoidf_(float x) {
    return 1.0f / (1.0f + expf(-x));
}

// One block per (b,h) row. Computes row-pass EDT (O(n) scans) and dice partial sums.
__global__ void row_edt_kernel(const float* __restrict__ pred,
                               const float* __restrict__ target,
                               const int* __restrict__ flg) {
    __shared__ float tsh[Wn];
    __shared__ int n1[Wn];   // nearest-one distance
    __shared__ int n0[Wn];   // nearest-zero distance
    __shared__ float rs[3][8];

    int row = blockIdx.x;            // 0..2047
    int b   = row >> 8;
    int tid = threadIdx.x;

    const float* trow = target + (size_t)row * Wn;
    const float* prow = pred   + (size_t)row * Wn;

    float t = trow[tid];
    tsh[tid] = t;

    // dice partials (sigmoid applied per from_logits flag)
    float p = prow[tid];
    if (flg[0]) p = sigmoidf_(p);
    float spt = p * t;
    float sp2 = p * p;
    float st  = t;

    // warp reduce
    unsigned lane = tid & 31u, wid = tid >> 5;
    #pragma unroll
    for (int o = 16; o; o >>= 1) {
        spt += __shfl_down_sync(0xffffffffu, spt, o);
        sp2 += __shfl_down_sync(0xffffffffu, sp2, o);
        st  += __shfl_down_sync(0xffffffffu, st,  o);
    }
    if (lane == 0) { rs[0][wid] = spt; rs[1][wid] = sp2; rs[2][wid] = st; }

    __syncthreads();

    if (tid == 0) {
        // block-level dice sums
        float A = 0.f, Bv = 0.f, C = 0.f;
        #pragma unroll
        for (int w = 0; w < 8; w++) { A += rs[0][w]; Bv += rs[1][w]; C += rs[2][w]; }
        atomicAdd(&acc_spt[b], (double)A);
        atomicAdd(&acc_sp2[b], (double)Bv);
        atomicAdd(&acc_st[b],  (double)C);

        // sequential two-sweep nearest distance (exact)
        int d1 = 1 << 20, d0 = 1 << 20;
        for (int j = 0; j < Wn; j++) {
            bool one = tsh[j] > 0.5f;
            d1 = one ? 0 : d1 + 1;
            d0 = one ? d0 + 1 : 0;
            n1[j] = d1; n0[j] = d0;
        }
        d1 = 1 << 20; d0 = 1 << 20;
        for (int j = Wn - 1; j >= 0; j--) {
            bool one = tsh[j] > 0.5f;
            d1 = one ? 0 : d1 + 1;
            d0 = one ? d0 + 1 : 0;
            n1[j] = min(n1[j], d1);
            n0[j] = min(n0[j], d0);
        }
    }
    __syncthreads();

    {
        int a1 = n1[tid];
        int a0 = n0[tid];
        size_t o = (size_t)row * Wn + tid;
        g_out_buf[o] = (a1 <= Wn - 1) ? (float)(a1 * a1) : INF_F;
        g_in_buf[o]  = (a0 <= Wn - 1) ? (float)(a0 * a0) : INF_F;
    }
}

// Column pass: brute-force min-plus along H on g_out/g_in, then boundary sum.
// Block handles (b, 8 columns). 256 threads: wl = tid%8 column, ig = tid/8,
// each thread computes outputs i = ig + 32k, k=0..7.
#define WT 8
__global__ void col_edt_kernel(const float* __restrict__ pred,
                               const int* __restrict__ flg) {
    __shared__ float csh[Hn * WT];          // c[j][w'] = g[b][j][w0+w'] + j^2
    __shared__ double red[8];

    int tid = threadIdx.x;
    int b   = blockIdx.x >> 5;              // 8 batches
    int w0  = (blockIdx.x & 31) * WT;       // 32 column-tiles
    int wl  = tid & (WT - 1);
    int ig  = tid >> 3;                     // 0..31

    float s[8];                             // accumulated distances per output i

    #pragma unroll
    for (int pass = 0; pass < 2; pass++) {
        const float* gb = (pass == 0) ? g_out_buf : g_in_buf;
        __syncthreads();
        // cooperative tile load, fold j^2
        #pragma unroll
        for (int r = 0; r < 8; r++) {
            int idx = tid + 256 * r;
            int j = idx >> 3;
            int wq = idx & (WT - 1);
            float v = gb[((size_t)(b * Hn + j)) * Wn + w0 + wq];
            float jf = (float)j;
            csh[idx] = fmaf(jf, jf, v);
        }
        __syncthreads();

        float m[8], a[8];
        #pragma unroll
        for (int k = 0; k < 8; k++) {
            m[k] = 3.0e38f;
            a[k] = -2.0f * (float)(ig + 32 * k);
        }
        float jf = 0.0f;
        for (int j = 0; j < Hn; j++) {
            float c = csh[j * WT + wl];
            #pragma unroll
            for (int k = 0; k < 8; k++)
                m[k] = fminf(m[k], fmaf(a[k], jf, c));
            jf += 1.0f;
        }
        #pragma unroll
        for (int k = 0; k < 8; k++) {
            float fi = (float)(ig + 32 * k);
            float h = fmaf(fi, fi, m[k]);   // exact for finite case
            float d = sqrtf(h);
            if (pass == 0) s[k] = d; else s[k] += d;
        }
    }

    // boundary loss partial: sum sigmoid(pred) * dist
    int fl = flg[0];
    double lsum = 0.0;
    #pragma unroll
    for (int k = 0; k < 8; k++) {
        int i = ig + 32 * k;
        float pv = pred[((size_t)(b * Hn + i)) * Wn + w0 + wl];
        if (fl) pv = sigmoidf_(pv);
        lsum += (double)(pv * s[k]);
    }
    // block reduce (double)
    unsigned lane = tid & 31u, wid = tid >> 5;
    #pragma unroll
    for (int o = 16; o; o >>= 1)
        lsum += __shfl_down_sync(0xffffffffu, lsum, o);
    if (lane == 0) red[wid] = lsum;
    __syncthreads();
    if (tid == 0) {
        double tot = 0.0;
        #pragma unroll
        for (int w = 0; w < 8; w++) tot += red[w];
        atomicAdd(&acc_bsum, tot);
    }
}

__global__ void finalize_kernel(float* __restrict__ out) {
    double d = 0.0;
    #pragma unroll
    for (int b = 0; b < Bn; b++) {
        double inter = 2.0 * acc_spt[b];
        double uni   = acc_sp2[b] + acc_st[b];
        d += 1.0 - (inter + 1e-6) / (uni + 1e-6);
    }
    d *= (1.0 / (double)Bn);
    double bl = acc_bsum * (1.0 / (double)NPIX);
    out[0] = (float)(d + bl);
}

extern "C" void kernel_launch(void* const* d_in, const int* in_sizes, int n_in,
                              void* d_out, int out_size) {
    const float* pred   = (const float*)d_in[0];
    const float* target = (const float*)d_in[1];
    const int*   flg    = (const int*)d_in[2];
    float* out = (float*)d_out;

    init_acc_kernel<<<1, 32>>>();
    row_edt_kernel<<<ROWS, Wn>>>(pred, target, flg);
    col_edt_kernel<<<Bn * (Wn / WT), 256>>>(pred, flg);
    finalize_kernel<<<1, 1>>>(out);
}

// round 3
// speedup vs baseline: 2.1726x; 2.1581x over previous
#include <cuda_runtime.h>
#include <math.h>

#define Bn 8
#define Hn 256
#define Wn 256
#define ROWS (Bn*Hn)          // 2048
#define NPIX (Bn*Hn*Wn)       // 524288
#define INF_F 1e10f
#define CW 16                 // columns per col-pass block
#define NCOLB (Bn*(Wn/CW))    // 128 col-pass blocks
#define RW 8                  // window radius; validity bound (RW+1)^2 = 81

// Scratch: row-pass squared distances, interleaved {d_to_one^2, d_to_zero^2}
__device__ float2 g_pair[NPIX];
// Per-row dice partials, per-block boundary partials (no atomics -> deterministic)
__device__ float  dice_spt[ROWS];
__device__ float  dice_sp2[ROWS];
__device__ float  dice_st [ROWS];
__device__ double bnd_part[NCOLB];

__device__ __forceinline__ float sigmoidf_(float x) {
    return 1.0f / (1.0f + expf(-x));
}

// Distance from bit position pos to the nearest set bit of the 256-bit mask m
// (optionally complemented). Returns >= 1<<20 if no set bit exists.
__device__ __forceinline__ int nearest_dist(const unsigned* m, int pos, bool inv) {
    int w = pos >> 5, b = pos & 31;
    unsigned mw = inv ? ~m[w] : m[w];
    int dl = 1 << 20, dr = 1 << 20;
    unsigned lo = mw & (0xffffffffu >> (31 - b));     // bits <= pos in own word
    if (lo) {
        dl = b - (31 - __clz(lo));
    } else {
        for (int ww = w - 1; ww >= 0; ww--) {
            unsigned v = inv ? ~m[ww] : m[ww];
            if (v) { dl = pos - (ww * 32 + 31 - __clz(v)); break; }
        }
    }
    unsigned hi = mw & (0xffffffffu << b);            // bits >= pos in own word
    if (hi) {
        dr = (__ffs(hi) - 1) - b;
    } else {
        for (int ww = w + 1; ww < 8; ww++) {
            unsigned v = inv ? ~m[ww] : m[ww];
            if (v) { dr = ww * 32 + (__ffs(v) - 1) - pos; break; }
        }
    }
    return min(dl, dr);
}

// One block per (b,h) row: dice partials + exact 1D row EDT via ballot bitmask.
__global__ void row_edt_kernel(const float* __restrict__ pred,
                               const float* __restrict__ target,
                               const int* __restrict__ flg) {
    __shared__ unsigned msk[8];
    __shared__ float rs[3][8];

    int row = blockIdx.x;
    int tid = threadIdx.x;

    float t = target[(size_t)row * Wn + tid];
    float p = pred  [(size_t)row * Wn + tid];
    if (flg[0]) p = sigmoidf_(p);

    unsigned lane = tid & 31u, wid = tid >> 5;
    unsigned bal = __ballot_sync(0xffffffffu, t > 0.5f);
    if (lane == 0) msk[wid] = bal;

    float spt = p * t, sp2 = p * p, st = t;
    #pragma unroll
    for (int o = 16; o; o >>= 1) {
        spt += __shfl_down_sync(0xffffffffu, spt, o);
        sp2 += __shfl_down_sync(0xffffffffu, sp2, o);
        st  += __shfl_down_sync(0xffffffffu, st,  o);
    }
    if (lane == 0) { rs[0][wid] = spt; rs[1][wid] = sp2; rs[2][wid] = st; }
    __syncthreads();

    if (tid == 0) {
        float A = 0.f, Bv = 0.f, C = 0.f;
        #pragma unroll
        for (int w = 0; w < 8; w++) { A += rs[0][w]; Bv += rs[1][w]; C += rs[2][w]; }
        dice_spt[row] = A; dice_sp2[row] = Bv; dice_st[row] = C;
    }

    // Row EDT: d1 = dist to nearest one (for EDT(1-t)), d0 = dist to nearest zero (EDT(t))
    int d1 = nearest_dist(msk, tid, false);
    int d0 = nearest_dist(msk, tid, true);
    float2 g;
    g.x = (d1 < Wn) ? (float)(d1 * d1) : INF_F;
    g.y = (d0 < Wn) ? (float)(d0 * d0) : INF_F;
    g_pair[(size_t)row * Wn + tid] = g;
}

// Column pass: windowed exact min-plus along H (radius RW, fallback to full
// loop when the validity bound fails), fused boundary-loss partial sum.
// Block = (b, 16-column tile). 256 threads: w = tid&15, i0 = (tid>>4)*16.
__global__ void col_edt_kernel(const float* __restrict__ pred,
                               const int* __restrict__ flg) {
    __shared__ float2 gsh[Hn * 17];     // padded stride 17 float2
    __shared__ double red[8];

    int tid = threadIdx.x;
    int b   = blockIdx.x >> 4;
    int w0  = (blockIdx.x & 15) * CW;

    #pragma unroll
    for (int r = 0; r < 16; r++) {
        int idx = tid + 256 * r;
        int j  = idx >> 4;
        int w  = idx & 15;
        gsh[j * 17 + w] = g_pair[((size_t)(b * Hn + j)) * Wn + w0 + w];
    }
    __syncthreads();

    int w  = tid & 15;
    int i0 = (tid >> 4) * 16;
    int fl = flg[0];
    bool interior = (i0 >= RW) && (i0 + 15 + RW <= Hn - 1);
    double bsum = 0.0;

    for (int k = 0; k < 16; k++) {
        int i = i0 + k;
        float mo = 3.0e38f, mi = 3.0e38f;
        if (interior) {
            #pragma unroll
            for (int dj = -RW; dj <= RW; dj++) {
                float2 c = gsh[(i + dj) * 17 + w];
                float q = (float)(dj * dj);
                mo = fminf(mo, c.x + q);
                mi = fminf(mi, c.y + q);
            }
        } else {
            #pragma unroll
            for (int dj = -RW; dj <= RW; dj++) {
                int j = i + dj;
                if ((unsigned)j < (unsigned)Hn) {
                    float2 c = gsh[j * 17 + w];
                    float q = (float)(dj * dj);
                    mo = fminf(mo, c.x + q);
                    mi = fminf(mi, c.y + q);
                }
            }
        }
        // Exactness: any j outside the window contributes >= (RW+1)^2 = 81.
        if (mo > 81.0f) {
            mo = 3.0e38f;
            for (int j = 0; j < Hn; j++) {
                float d = (float)(i - j);
                mo = fminf(mo, fmaf(d, d, gsh[j * 17 + w].x));
            }
        }
        if (mi > 81.0f) {
            mi = 3.0e38f;
            for (int j = 0; j < Hn; j++) {
                float d = (float)(i - j);
                mi = fminf(mi, fmaf(d, d, gsh[j * 17 + w].y));
            }
        }
        float s = sqrtf(mo) + sqrtf(mi);
        float pv = pred[((size_t)(b * Hn + i)) * Wn + w0 + w];
        if (fl) pv = sigmoidf_(pv);
        bsum += (double)(pv * s);
    }

    unsigned lane = tid & 31u, wid = tid >> 5;
    #pragma unroll
    for (int o = 16; o; o >>= 1)
        bsum += __shfl_down_sync(0xffffffffu, bsum, o);
    if (lane == 0) red[wid] = bsum;
    __syncthreads();
    if (tid == 0) {
        double tot = 0.0;
        #pragma unroll
        for (int ww = 0; ww < 8; ww++) tot += red[ww];
        bnd_part[blockIdx.x] = tot;
    }
}

// Parallel finalize: warp b reduces batch b's dice partials; boundary partials
// reduced block-wide; thread 0 combines.
__global__ void finalize_kernel(float* __restrict__ out) {
    __shared__ double dsh[8];
    __shared__ double bsh[8];
    int tid = threadIdx.x;
    int lane = tid & 31, wid = tid >> 5;

    double a = 0.0, bv = 0.0, c = 0.0;
    for (int r = lane; r < Hn; r += 32) {
        int row = wid * Hn + r;
        a  += (double)dice_spt[row];
        bv += (double)dice_sp2[row];
        c  += (double)dice_st [row];
    }
    #pragma unroll
    for (int o = 16; o; o >>= 1) {
        a  += __shfl_down_sync(0xffffffffu, a,  o);
        bv += __shfl_down_sync(0xffffffffu, bv, o);
        c  += __shfl_down_sync(0xffffffffu, c,  o);
    }
    if (lane == 0)
        dsh[wid] = 1.0 - (2.0 * a + 1e-6) / (bv + c + 1e-6);

    double bd = (tid < NCOLB) ? bnd_part[tid] : 0.0;
    #pragma unroll
    for (int o = 16; o; o >>= 1)
        bd += __shfl_down_sync(0xffffffffu, bd, o);
    if (lane == 0) bsh[wid] = bd;
    __syncthreads();

    if (tid == 0) {
        double d = 0.0, bb = 0.0;
        #pragma unroll
        for (int ww = 0; ww < 8; ww++) { d += dsh[ww]; bb += bsh[ww]; }
        out[0] = (float)(d * (1.0 / (double)Bn) + bb * (1.0 / (double)NPIX));
    }
}

extern "C" void kernel_launch(void* const* d_in, const int* in_sizes, int n_in,
                              void* d_out, int out_size) {
    const float* pred   = (const float*)d_in[0];
    const float* target = (const float*)d_in[1];
    const int*   flg    = (const int*)d_in[2];
    float* out = (float*)d_out;

    row_edt_kernel<<<ROWS, Wn>>>(pred, target, flg);
    col_edt_kernel<<<NCOLB, 256>>>(pred, flg);
    finalize_kernel<<<1, 256>>>(out);
}

// round 4
// speedup vs baseline: 3.1154x; 1.4339x over previous
#include <cuda_runtime.h>
#include <math.h>

#define Bn 8
#define Hn 256
#define Wn 256
#define NPIX (Bn*Hn*Wn)       // 524288
#define INF_F 1e10f
#define RW 4                  // window radius; accept bound (RW+1)^2 = 25
#define RW_BOUND ((RW+1)*(RW+1))
#define SR 16                 // strip rows per block
#define MR (SR + 2*RW)        // 24 mask/g rows per block
#define NBLK (Bn * (Hn/SR))   // 128 blocks

// Per-block partials (disjoint pixel coverage -> no atomics, deterministic)
__device__ float  d_spt[NBLK];
__device__ float  d_sp2[NBLK];
__device__ float  d_st [NBLK];
__device__ double d_bnd[NBLK];

// Distance (clamped to 7) from offset-0 (bit 15) to nearest set bit of v.
// v: bit (15+t) = candidate at offset t, t in [-15, 16].
__device__ __forceinline__ int win_dist(unsigned v) {
    unsigned left = v << 16;                 // bit 31-d = offset -d
    int dl = left ? __clz(left) : 99;
    unsigned right = v >> 15;                // bit d = offset +d
    int dr = right ? (__ffs(right) - 1) : 99;
    return min(min(dl, dr), 7);
}

// Exact global fallback (replicates reference min-plus bitwise; never taken
// for benign inputs, keeps worst-case exactness).
__device__ __noinline__ float fb_min(const float* __restrict__ timg,
                                     int i, int w, bool want_one) {
    float m = 3.0e38f;
    for (int j = 0; j < Hn; j++) {
        int best = 1 << 20;
        for (int c = 0; c < Wn; c++) {
            float tv = timg[j * Wn + c];
            bool hit = want_one ? (tv > 0.5f) : (tv <= 0.5f);
            if (hit) best = min(best, abs(w - c));
        }
        float g = (best < Wn) ? (float)(best * best) : INF_F;
        float dj = (float)(i - j);
        m = fminf(m, fmaf(dj, dj, g));
    }
    return m;
}

// One block per (batch, 16-row strip). Does everything: masks, row EDT,
// windowed column EDT, dice partials, boundary partial.
__global__ void fused_kernel(const float* __restrict__ pred,
                             const float* __restrict__ target,
                             const int* __restrict__ flg) {
    __shared__ unsigned msk[MR][8];
    __shared__ uchar2 gsh[MR][Wn];       // clamped row-dists {to-one, to-zero}
    __shared__ float rsf[3][8];
    __shared__ double rsd[8];

    int tid  = threadIdx.x;
    int lane = tid & 31, wwp = tid >> 5;
    int b    = blockIdx.x >> 4;
    int i0   = (blockIdx.x & 15) * SR;
    int j0   = i0 - RW;
    const float* timg = target + (size_t)b * Hn * Wn;

    // --- build target bitmasks for the 24 halo rows (warp ww: rows 3ww..3ww+2)
    #pragma unroll
    for (int rr = 0; rr < 3; rr++) {
        int r = wwp * 3 + rr;
        int j = j0 + r;
        if ((unsigned)j < (unsigned)Hn) {
            #pragma unroll
            for (int seg = 0; seg < 8; seg++) {
                float tv = timg[j * Wn + seg * 32 + lane];
                unsigned bal = __ballot_sync(0xffffffffu, tv > 0.5f);
                if (lane == 0) msk[r][seg] = bal;
            }
        }
    }
    __syncthreads();

    // --- per-column clamped row distances for all 24 rows (thread = column)
    int w  = tid;
    int ww = w >> 5, bb = w & 31;
    #pragma unroll 4
    for (int r = 0; r < MR; r++) {
        int j = j0 + r;
        uchar2 g;
        if ((unsigned)j < (unsigned)Hn) {
            const unsigned* m = msk[r];
            unsigned mw = m[ww];
            unsigned lo = (ww >= 1) ? m[ww - 1] : 0u;
            unsigned hi = (ww <= 6) ? m[ww + 1] : 0u;
            unsigned v, vm;
            if (bb >= 15) {
                v  = __funnelshift_r(mw, hi, bb - 15);
                vm = __funnelshift_r(0xffffffffu, (ww <= 6) ? 0xffffffffu : 0u, bb - 15);
            } else {
                v  = __funnelshift_r(lo, mw, bb + 17);
                vm = __funnelshift_r((ww >= 1) ? 0xffffffffu : 0u, 0xffffffffu, bb + 17);
            }
            g.x = (unsigned char)win_dist(v);             // dist to nearest 1
            g.y = (unsigned char)win_dist((~v) & vm);     // dist to nearest 0
        } else {
            g.x = 7; g.y = 7;   // out-of-image: contribution >= 49, never accepted
        }
        gsh[r][w] = g;
    }
    __syncthreads();

    // --- windowed column pass + dice + boundary, thread = column, 16 rows each
    int fl = flg[0];
    float spt = 0.f, sp2 = 0.f, stt = 0.f;
    double bsum = 0.0;

    #pragma unroll
    for (int k = 0; k < SR; k++) {
        int mo = 0x7fffffff, mi = 0x7fffffff;
        #pragma unroll
        for (int u = 0; u < 2 * RW + 1; u++) {
            uchar2 c = gsh[k + u][w];
            int q = (RW - u) * (RW - u);
            int dx = c.x, dy = c.y;
            mo = min(mo, dx * dx + q);
            mi = min(mi, dy * dy + q);
        }
        int i = i0 + k;
        // window min <= 25 is provably the exact global min (outside >= 25)
        float fmo = (mo <= RW_BOUND) ? (float)mo : fb_min(timg, i, w, true);
        float fmi = (mi <= RW_BOUND) ? (float)mi : fb_min(timg, i, w, false);
        float dist = sqrtf(fmo) + sqrtf(fmi);

        float p = pred[(((size_t)b * Hn) + i) * Wn + w];
        if (fl) p = __fdividef(1.0f, 1.0f + __expf(-p));
        float tb = (float)((msk[k + RW][ww] >> bb) & 1u);

        spt += p * tb;
        sp2 += p * p;
        stt += tb;
        bsum += (double)(p * dist);
    }

    // --- block reduction
    #pragma unroll
    for (int o = 16; o; o >>= 1) {
        spt  += __shfl_down_sync(0xffffffffu, spt,  o);
        sp2  += __shfl_down_sync(0xffffffffu, sp2,  o);
        stt  += __shfl_down_sync(0xffffffffu, stt,  o);
        bsum += __shfl_down_sync(0xffffffffu, bsum, o);
    }
    if (lane == 0) { rsf[0][wwp] = spt; rsf[1][wwp] = sp2; rsf[2][wwp] = stt; rsd[wwp] = bsum; }
    __syncthreads();
    if (tid == 0) {
        float A = 0.f, Bv = 0.f, C = 0.f; double D = 0.0;
        #pragma unroll
        for (int q = 0; q < 8; q++) { A += rsf[0][q]; Bv += rsf[1][q]; C += rsf[2][q]; D += rsd[q]; }
        d_spt[blockIdx.x] = A; d_sp2[blockIdx.x] = Bv; d_st[blockIdx.x] = C;
        d_bnd[blockIdx.x] = D;
    }
}

__global__ void finalize_kernel(float* __restrict__ out) {
    __shared__ double dsh[8], bsh[8];
    int tid = threadIdx.x, lane = tid & 31, wq = tid >> 5;

    // dice: warp wq reduces batch wq's 16 block-partials
    double a = 0.0, bv = 0.0, c = 0.0;
    if (lane < 16) {
        int blk = wq * 16 + lane;
        a  = (double)d_spt[blk];
        bv = (double)d_sp2[blk];
        c  = (double)d_st [blk];
    }
    #pragma unroll
    for (int o = 8; o; o >>= 1) {
        a  += __shfl_down_sync(0xffffffffu, a,  o);
        bv += __shfl_down_sync(0xffffffffu, bv, o);
        c  += __shfl_down_sync(0xffffffffu, c,  o);
    }
    if (lane == 0) dsh[wq] = 1.0 - (2.0 * a + 1e-6) / (bv + c + 1e-6);

    // boundary: 128 partials over first 128 threads
    double bd = (tid < NBLK) ? d_bnd[tid] : 0.0;
    #pragma unroll
    for (int o = 16; o; o >>= 1)
        bd += __shfl_down_sync(0xffffffffu, bd, o);
    if (lane == 0) bsh[wq] = bd;
    __syncthreads();

    if (tid == 0) {
        double d = 0.0, bb = 0.0;
        #pragma unroll
        for (int q = 0; q < 8; q++) { d += dsh[q]; bb += bsh[q]; }
        out[0] = (float)(d * (1.0 / (double)Bn) + bb * (1.0 / (double)NPIX));
    }
}

extern "C" void kernel_launch(void* const* d_in, const int* in_sizes, int n_in,
                              void* d_out, int out_size) {
    const float* pred   = (const float*)d_in[0];
    const float* target = (const float*)d_in[1];
    const int*   flg    = (const int*)d_in[2];
    float* out = (float*)d_out;

    fused_kernel<<<NBLK, 256>>>(pred, target, flg);
    finalize_kernel<<<1, 256>>>(out);
}

// round 5
// speedup vs baseline: 4.2424x; 1.3617x over previous
#include <cuda_runtime.h>
#include <math.h>

#define Bn 8
#define Hn 256
#define Wn 256
#define NPIX (Bn*Hn*Wn)       // 524288
#define INF_F 1e10f
#define RW 4                  // window radius; accept bound (RW+1)^2 = 25
#define RW_BOUND ((RW+1)*(RW+1))
#define SR 8                  // strip rows per block
#define MR (SR + 2*RW)        // 16 halo rows per block
#define SPB (Hn/SR)           // 32 strips per batch
#define NBLK (Bn * SPB)       // 256 blocks

// Per-block partials (disjoint coverage -> no atomics on data, deterministic)
__device__ float  d_spt[NBLK];
__device__ float  d_sp2[NBLK];
__device__ float  d_st [NBLK];
__device__ double d_bnd[NBLK];
__device__ unsigned d_cnt = 0;   // last-block-done counter (reset by last block)

// Distance (clamped to 7) from offset-0 (bit 15) to nearest set bit of v.
__device__ __forceinline__ int win_dist(unsigned v) {
    unsigned left = v << 16;                 // bit 31-d = offset -d
    int dl = left ? __clz(left) : 99;
    unsigned right = v >> 15;                // bit d = offset +d
    int dr = right ? (__ffs(right) - 1) : 99;
    return min(min(dl, dr), 7);
}

// Exact global fallback (bitwise-matches reference min-plus; never taken for
// benign inputs, preserves worst-case exactness).
__device__ __noinline__ float fb_min(const float* __restrict__ timg,
                                     int i, int w, bool want_one) {
    float m = 3.0e38f;
    for (int j = 0; j < Hn; j++) {
        int best = 1 << 20;
        for (int c = 0; c < Wn; c++) {
            float tv = timg[j * Wn + c];
            bool hit = want_one ? (tv > 0.5f) : (tv <= 0.5f);
            if (hit) best = min(best, abs(w - c));
        }
        float g = (best < Wn) ? (float)(best * best) : INF_F;
        float dj = (float)(i - j);
        m = fminf(m, fmaf(dj, dj, g));
    }
    return m;
}

__global__ void fused_kernel(const float* __restrict__ pred,
                             const float* __restrict__ target,
                             const int* __restrict__ flg,
                             float* __restrict__ out) {
    __shared__ unsigned msk[MR][8];
    __shared__ unsigned gsh[MR][Wn];     // per row/col: dx^2 | dy^2<<16
    __shared__ float rsf[3][8];
    __shared__ double rsd[8];
    __shared__ unsigned is_last_sh;

    int tid  = threadIdx.x;
    int lane = tid & 31, wwp = tid >> 5;
    int b    = blockIdx.x >> 5;              // batch
    int i0   = (blockIdx.x & 31) * SR;       // strip start row
    int j0   = i0 - RW;
    const float* timg = target + (size_t)b * Hn * Wn;
    int fl = flg[0];

    // --- build target bitmasks for the 16 halo rows (warp wwp: rows 2wwp, 2wwp+1)
    #pragma unroll
    for (int rr = 0; rr < 2; rr++) {
        int r = wwp * 2 + rr;
        int j = j0 + r;
        if ((unsigned)j < (unsigned)Hn) {
            #pragma unroll
            for (int seg = 0; seg < 8; seg++) {
                float tv = timg[j * Wn + seg * 32 + lane];
                unsigned bal = __ballot_sync(0xffffffffu, tv > 0.5f);
                if (lane == 0) msk[r][seg] = bal;
            }
        }
    }

    // prefetch pred for this thread's column (overlap with ALU phases below)
    int w = tid;
    float pv[SR];
    #pragma unroll
    for (int k = 0; k < SR; k++)
        pv[k] = pred[(((size_t)b * Hn) + i0 + k) * Wn + w];

    __syncthreads();

    // --- per-column clamped row distances, packed dx^2 | dy^2<<16
    int ww = w >> 5, bb = w & 31;
    #pragma unroll 4
    for (int r = 0; r < MR; r++) {
        int j = j0 + r;
        unsigned packed;
        if ((unsigned)j < (unsigned)Hn) {
            const unsigned* m = msk[r];
            unsigned mw = m[ww];
            unsigned lo = (ww >= 1) ? m[ww - 1] : 0u;
            unsigned hi = (ww <= 6) ? m[ww + 1] : 0u;
            unsigned v, vm;
            if (bb >= 15) {
                v  = __funnelshift_r(mw, hi, bb - 15);
                vm = __funnelshift_r(0xffffffffu, (ww <= 6) ? 0xffffffffu : 0u, bb - 15);
            } else {
                v  = __funnelshift_r(lo, mw, bb + 17);
                vm = __funnelshift_r((ww >= 1) ? 0xffffffffu : 0u, 0xffffffffu, bb + 17);
            }
            int dx = win_dist(v);               // dist to nearest 1
            int dy = win_dist((~v) & vm);       // dist to nearest 0
            packed = (unsigned)(dx * dx) | ((unsigned)(dy * dy) << 16);
        } else {
            packed = 49u | (49u << 16);         // >= 49: never accepted
        }
        gsh[r][w] = packed;
    }
    __syncthreads();

    // --- windowed column pass + dice + boundary (thread = column, SR rows)
    float spt = 0.f, sp2 = 0.f, stt = 0.f;
    double bsum = 0.0;

    #pragma unroll
    for (int k = 0; k < SR; k++) {
        // m = per-halfword min over u of (d^2 + (u-RW)^2), both EDTs at once
        unsigned m = gsh[k][w] + ((RW * RW) | ((RW * RW) << 16));
        #pragma unroll
        for (int u = 1; u <= 2 * RW; u++) {
            int q = (u - RW) * (u - RW);
            m = __vminu2(m, gsh[k + u][w] + (unsigned)(q | (q << 16)));
        }
        int mo = (int)(m & 0xffffu);
        int mi = (int)(m >> 16);
        int i = i0 + k;
        // window min <= 25 is provably the exact global min (outside >= 25)
        float fmo = (mo <= RW_BOUND) ? (float)mo : fb_min(timg, i, w, true);
        float fmi = (mi <= RW_BOUND) ? (float)mi : fb_min(timg, i, w, false);
        float dist = sqrtf(fmo) + sqrtf(fmi);

        float p = pv[k];
        if (fl) p = __fdividef(1.0f, 1.0f + __expf(-p));
        float tb = (float)((msk[k + RW][ww] >> bb) & 1u);

        spt += p * tb;
        sp2 += p * p;
        stt += tb;
        bsum += (double)(p * dist);
    }

    // --- block reduction
    #pragma unroll
    for (int o = 16; o; o >>= 1) {
        spt  += __shfl_down_sync(0xffffffffu, spt,  o);
        sp2  += __shfl_down_sync(0xffffffffu, sp2,  o);
        stt  += __shfl_down_sync(0xffffffffu, stt,  o);
        bsum += __shfl_down_sync(0xffffffffu, bsum, o);
    }
    if (lane == 0) { rsf[0][wwp] = spt; rsf[1][wwp] = sp2; rsf[2][wwp] = stt; rsd[wwp] = bsum; }
    __syncthreads();

    if (tid == 0) {
        float A = 0.f, Bv = 0.f, C = 0.f; double D = 0.0;
        #pragma unroll
        for (int q = 0; q < 8; q++) { A += rsf[0][q]; Bv += rsf[1][q]; C += rsf[2][q]; D += rsd[q]; }
        d_spt[blockIdx.x] = A; d_sp2[blockIdx.x] = Bv; d_st[blockIdx.x] = C;
        d_bnd[blockIdx.x] = D;
        __threadfence();
        unsigned prev = atomicAdd(&d_cnt, 1u);
        is_last_sh = (prev == NBLK - 1) ? 1u : 0u;
    }
    __syncthreads();

    // --- last block finalizes (no extra kernel)
    if (is_last_sh) {
        __shared__ double dsh[8], bsh[8];
        // dice: warp wwp reduces batch wwp's 32 strip-partials
        int blk = wwp * SPB + lane;
        double a  = (double)__ldcg(&d_spt[blk]);
        double bv = (double)__ldcg(&d_sp2[blk]);
        double c  = (double)__ldcg(&d_st [blk]);
        #pragma unroll
        for (int o = 16; o; o >>= 1) {
            a  += __shfl_down_sync(0xffffffffu, a,  o);
            bv += __shfl_down_sync(0xffffffffu, bv, o);
            c  += __shfl_down_sync(0xffffffffu, c,  o);
        }
        if (lane == 0) dsh[wwp] = 1.0 - (2.0 * a + 1e-6) / (bv + c + 1e-6);

        // boundary: 256 partials across 256 threads
        double bd = __ldcg(&d_bnd[tid]);
        #pragma unroll
        for (int o = 16; o; o >>= 1)
            bd += __shfl_down_sync(0xffffffffu, bd, o);
        if (lane == 0) bsh[wwp] = bd;
        __syncthreads();

        if (tid == 0) {
            double d = 0.0, bbv = 0.0;
            #pragma unroll
            for (int q = 0; q < 8; q++) { d += dsh[q]; bbv += bsh[q]; }
            out[0] = (float)(d * (1.0 / (double)Bn) + bbv * (1.0 / (double)NPIX));
            d_cnt = 0;   // reset for next graph replay (deterministic)
        }
    }
}

extern "C" void kernel_launch(void* const* d_in, const int* in_sizes, int n_in,
                              void* d_out, int out_size) {
    const float* pred   = (const float*)d_in[0];
    const float* target = (const float*)d_in[1];
    const int*   flg    = (const int*)d_in[2];
    float* out = (float*)d_out;

    fused_kernel<<<NBLK, 256>>>(pred, target, flg, out);
}